// round 5
// baseline (speedup 1.0000x reference)
#include <cuda_runtime.h>
#include <cstdint>

// Problem constants (fixed by the reference).
#define N_NODES 100000
#define N_EDGES 1600000
#define NF 32

#define EPT 4                       // edges per thread in scatter
#define ECHUNK (N_EDGES / EPT)      // 400000

// Scratch (device globals — no allocation allowed in kernel_launch).
__device__ float g_deg[N_NODES];
__device__ float g_dinv[N_NODES];

// Phase 0: init degree with the self-loop contribution.
__global__ void k_init_deg() {
    int i = blockIdx.x * blockDim.x + threadIdx.x;
    if (i < N_NODES) g_deg[i] = 1.0f;
}

// Phase 1: in-degree over dst (edge_index row 1, int32). int4-vectorized:
// 4 edges per thread, one 16B coalesced load + 4 reductions.
__global__ void k_count_deg(const int* __restrict__ ei) {
    int t = blockIdx.x * blockDim.x + threadIdx.x;
    if (t < N_EDGES / 4) {
        int4 d = __ldg((const int4*)(ei + N_EDGES) + t);
        atomicAdd(&g_deg[d.x], 1.0f);
        atomicAdd(&g_deg[d.y], 1.0f);
        atomicAdd(&g_deg[d.z], 1.0f);
        atomicAdd(&g_deg[d.w], 1.0f);
    }
}

// Phase 2: dinv = deg^-0.5, and seed out with the self-loop term x[i]/deg[i].
__global__ void k_dinv_self(const float* __restrict__ x, float* __restrict__ out) {
    int i = blockIdx.x * blockDim.x + threadIdx.x;
    if (i < N_NODES) {
        float d = g_deg[i];           // >= 1 always (self loop)
        float di = rsqrtf(d);
        g_dinv[i] = di;
        float w = di * di;            // = 1/deg
        const float4* xi = (const float4*)(x + (size_t)i * NF);
        float4* oi = (float4*)(out + (size_t)i * NF);
        #pragma unroll
        for (int k = 0; k < NF / 4; k++) {
            float4 v = xi[k];
            v.x *= w; v.y *= w; v.z *= w; v.w *= w;
            oi[k] = v;
        }
    }
}

// Phase 3: edge scatter, EPT edges per thread for MLP. 8 lanes per edge,
// each lane owns one float4 (16 B) of the 128 B feature row. All loads of
// one stage are issued back-to-back so 4-8 independent requests are in
// flight per thread (the R4 profile showed issue=27%/occ=80%: pure
// latency-bound with MLP=1).
__global__ void __launch_bounds__(256)
k_scatter(const float* __restrict__ x,
          const int* __restrict__ ei,
          float* __restrict__ out) {
    int tid = blockIdx.x * blockDim.x + threadIdx.x;
    int t8 = tid >> 3;          // [0, ECHUNK)
    int f4 = tid & 7;
    if (t8 >= ECHUNK) return;

    int src[EPT], dst[EPT];
    #pragma unroll
    for (int k = 0; k < EPT; k++) {
        int e = t8 + k * ECHUNK;          // coalesced per k
        src[k] = __ldg(&ei[e]);
        dst[k] = __ldg(&ei[N_EDGES + e]);
    }

    float ws[EPT], wd[EPT];
    #pragma unroll
    for (int k = 0; k < EPT; k++) {
        ws[k] = __ldg(&g_dinv[src[k]]);
        wd[k] = __ldg(&g_dinv[dst[k]]);
    }

    float4 v[EPT];
    #pragma unroll
    for (int k = 0; k < EPT; k++) {
        v[k] = __ldg((const float4*)(x + (size_t)src[k] * NF) + f4);
    }

    #pragma unroll
    for (int k = 0; k < EPT; k++) {
        float w = ws[k] * wd[k];
        float a = v[k].x * w, b = v[k].y * w, c = v[k].z * w, d = v[k].w * w;
        float* op = out + (size_t)dst[k] * NF + (size_t)f4 * 4;
        asm volatile("red.global.add.v4.f32 [%0], {%1, %2, %3, %4};"
                     :: "l"(op), "f"(a), "f"(b), "f"(c), "f"(d) : "memory");
    }
}

extern "C" void kernel_launch(void* const* d_in, const int* in_sizes, int n_in,
                              void* d_out, int out_size) {
    const float* x  = (const float*)d_in[0];   // [N_NODES, 32] f32
    const int*   ei = (const int*)d_in[1];     // [2, N_EDGES] int32
    float* out = (float*)d_out;                // [N_NODES, 32] f32

    const int T = 256;
    k_init_deg<<<(N_NODES + T - 1) / T, T>>>();
    k_count_deg<<<(N_EDGES / 4 + T - 1) / T, T>>>(ei);
    k_dinv_self<<<(N_NODES + T - 1) / T, T>>>(x, out);

    long long work = (long long)ECHUNK * 8;
    k_scatter<<<(unsigned)((work + T - 1) / T), T>>>(x, ei, out);
}

// round 6
// speedup vs baseline: 1.1326x; 1.1326x over previous
#include <cuda_runtime.h>
#include <cstdint>

// Problem constants (fixed by the reference).
#define N_NODES 100000
#define N_EDGES 1600000
#define NF 32

#define EPT 4                       // edges per thread in scatter
#define ECHUNK (N_EDGES / EPT)      // 400000

// Scratch (device globals — no allocation allowed in kernel_launch).
__device__ float g_deg[N_NODES];
__device__ float g_dinv[N_NODES];
__device__ float g_xs[N_NODES * NF];   // xs[i] = dinv[i] * x[i]

// Phase 0: init degree with the self-loop contribution.
__global__ void k_init_deg() {
    int i = blockIdx.x * blockDim.x + threadIdx.x;
    if (i < N_NODES) g_deg[i] = 1.0f;
}

// Phase 1: in-degree over dst (edge_index row 1, int32). int4-vectorized.
__global__ void k_count_deg(const int* __restrict__ ei) {
    int t = blockIdx.x * blockDim.x + threadIdx.x;
    if (t < N_EDGES / 4) {
        int4 d = __ldg((const int4*)(ei + N_EDGES) + t);
        atomicAdd(&g_deg[d.x], 1.0f);
        atomicAdd(&g_deg[d.y], 1.0f);
        atomicAdd(&g_deg[d.z], 1.0f);
        atomicAdd(&g_deg[d.w], 1.0f);
    }
}

// Phase 2: dinv = deg^-0.5; xs = dinv * x; seed out = xs (absorbs the
// self-loop term after the final dinv[dst] scaling). One thread per float4
// for full coalescing; 8 lanes of a node redundantly compute rsqrt, lane 0
// writes g_dinv.
__global__ void k_dinv_xs(const float* __restrict__ x, float* __restrict__ out) {
    int t = blockIdx.x * blockDim.x + threadIdx.x;   // [0, N*8)
    if (t >= N_NODES * (NF / 4)) return;
    int node = t >> 3;
    float di = rsqrtf(g_deg[node]);
    if ((t & 7) == 0) g_dinv[node] = di;
    float4 v = __ldg((const float4*)x + t);
    v.x *= di; v.y *= di; v.z *= di; v.w *= di;
    ((float4*)g_xs)[t] = v;
    ((float4*)out)[t]  = v;
}

// Phase 3: unweighted edge scatter: out[dst] += xs[src]. 8 lanes per edge,
// each lane owns one float4 of the 128 B row; EPT edges per thread for MLP.
// No weight loads, no FP math — pure gather -> red chain.
__global__ void __launch_bounds__(256)
k_scatter(const int* __restrict__ ei, float* __restrict__ out) {
    int tid = blockIdx.x * blockDim.x + threadIdx.x;
    int t8 = tid >> 3;          // [0, ECHUNK)
    int f4 = tid & 7;
    if (t8 >= ECHUNK) return;

    int src[EPT], dst[EPT];
    #pragma unroll
    for (int k = 0; k < EPT; k++) {
        int e = t8 + k * ECHUNK;          // coalesced per k
        src[k] = __ldg(&ei[e]);
        dst[k] = __ldg(&ei[N_EDGES + e]);
    }

    float4 v[EPT];
    #pragma unroll
    for (int k = 0; k < EPT; k++) {
        v[k] = __ldg((const float4*)(g_xs + (size_t)src[k] * NF) + f4);
    }

    #pragma unroll
    for (int k = 0; k < EPT; k++) {
        float* op = out + (size_t)dst[k] * NF + (size_t)f4 * 4;
        asm volatile("red.global.add.v4.f32 [%0], {%1, %2, %3, %4};"
                     :: "l"(op), "f"(v[k].x), "f"(v[k].y), "f"(v[k].z), "f"(v[k].w)
                     : "memory");
    }
}

// Phase 4: out[i] *= dinv[i].
__global__ void k_final(float* __restrict__ out) {
    int t = blockIdx.x * blockDim.x + threadIdx.x;   // [0, N*8)
    if (t >= N_NODES * (NF / 4)) return;
    int node = t >> 3;
    float di = __ldg(&g_dinv[node]);
    float4 v = ((float4*)out)[t];
    v.x *= di; v.y *= di; v.z *= di; v.w *= di;
    ((float4*)out)[t] = v;
}

extern "C" void kernel_launch(void* const* d_in, const int* in_sizes, int n_in,
                              void* d_out, int out_size) {
    const float* x  = (const float*)d_in[0];   // [N_NODES, 32] f32
    const int*   ei = (const int*)d_in[1];     // [2, N_EDGES] int32
    float* out = (float*)d_out;                // [N_NODES, 32] f32

    const int T = 256;
    k_init_deg<<<(N_NODES + T - 1) / T, T>>>();
    k_count_deg<<<(N_EDGES / 4 + T - 1) / T, T>>>(ei);

    int nwork = N_NODES * (NF / 4);
    k_dinv_xs<<<(nwork + T - 1) / T, T>>>(x, out);

    long long work = (long long)ECHUNK * 8;
    k_scatter<<<(unsigned)((work + T - 1) / T), T>>>(ei, out);

    k_final<<<(nwork + T - 1) / T, T>>>(out);
}